// round 9
// baseline (speedup 1.0000x reference)
#include <cuda_runtime.h>

#define BATCH 2048
#define ISIZE 2048
#define OSIZE 2048
#define NIN   6
#define KTAB  64

typedef unsigned long long ull;

// Static scratch: transposed x, xT[m][b]  (16 MB)
__device__ float g_xT[(size_t)ISIZE * BATCH];

__device__ __forceinline__ ull pack2(float lo, float hi) {
    ull r;
    asm("mov.b64 %0, {%1, %2};" : "=l"(r) : "f"(lo), "f"(hi));
    return r;
}
__device__ __forceinline__ ull fma2(ull a, ull b, ull c) {
    ull r;
    asm("fma.rn.f32x2 %0, %1, %2, %3;" : "=l"(r) : "l"(a), "l"(b), "l"(c));
    return r;
}
__device__ __forceinline__ ull mul2(ull a, ull b) {
    ull r;
    asm("mul.rn.f32x2 %0, %1, %2;" : "=l"(r) : "l"(a), "l"(b));
    return r;
}
__device__ __forceinline__ float2 unpack2(ull v) {
    float2 f;
    asm("mov.b64 {%0, %1}, %2;" : "=f"(f.x), "=f"(f.y) : "l"(v));
    return f;
}

// ---------------------------------------------------------------------------
// Kernel 1: transpose x [BATCH][ISIZE] -> g_xT [ISIZE][BATCH]
// ---------------------------------------------------------------------------
__global__ void transpose_kernel(const float* __restrict__ x) {
    __shared__ float tile[32][33];
    int bx = blockIdx.x * 32;
    int by = blockIdx.y * 32;
    int tx = threadIdx.x, ty = threadIdx.y;
#pragma unroll
    for (int j = 0; j < 32; j += 8)
        tile[ty + j][tx] = x[(size_t)(by + ty + j) * ISIZE + bx + tx];
    __syncthreads();
#pragma unroll
    for (int j = 0; j < 32; j += 8)
        g_xT[(size_t)(bx + ty + j) * BATCH + by + tx] = tile[tx][ty + j];
}

// ---------------------------------------------------------------------------
// Kernel 2: LUT evaluation.
//   Thread tile: 2 outputs x 8 batches (4 f32x2 pairs -> 4 independent fma
//   chains for ILP; each coefficient LDS.128 amortized over 4 pairs).
//   CTA: 128 threads = 1024 batches x 2 outputs. Grid 1024 x 2 = 2048 CTAs.
//   Gathers: per dim one ulonglong2 (16B) x2 -> pairs arrive pre-packed.
//   Levels 0-1: bilinear quads (Mobius coeffs a,d0,d1,d01 in shared).
//   Levels 2-5: depth-first lerp tree, 4-wide.
// ---------------------------------------------------------------------------
#define OT      2
#define THREADS 128
#define BPT     8                 // batches per thread
#define BT      (THREADS * BPT)   // 1024
#define NQ      (KTAB / 4)        // 16 quads

__global__ __launch_bounds__(THREADS, 4)
void lut_kernel(const float* __restrict__ table,
                const void* __restrict__ mraw,
                float* __restrict__ out) {
    __shared__ __align__(16) float4 s_c[OT][NQ];   // (a, d0, d1, d01)
    __shared__ int s_off[OT][NIN];
    __shared__ int s_is64;

    const int tid   = threadIdx.x;
    const int obase = blockIdx.x * OT;
    const int bbase = blockIdx.y * BT;

    // Detect mapping dtype: int64 values < 2048 => odd 32-bit words are 0.
    const int* w32 = (const int*)mraw;
    if (tid == 0) {
        int z = 1;
#pragma unroll
        for (int i = 1; i < 16; i += 2) z &= (w32[i] == 0);
        s_is64 = z;
    }
    __syncthreads();
    const int is64 = s_is64;

    if (tid < OT * NIN) {
        int idx = (obase + tid / NIN) * NIN + (tid % NIN);
        int m = is64 ? (int)((const long long*)mraw)[idx] : w32[idx];
        s_off[tid / NIN][tid % NIN] = m * BATCH + bbase;
    }

    if (tid < OT * NQ) {
        int o = tid >> 4, q = tid & (NQ - 1);
        const float* t = table + (size_t)(obase + o) * KTAB + 4 * q;
        float s0 = 1.0f / (1.0f + __expf(-t[0]));   // x0=0, x1=0
        float s1 = 1.0f / (1.0f + __expf(-t[1]));   // x0=1, x1=0
        float s2 = 1.0f / (1.0f + __expf(-t[2]));   // x0=0, x1=1
        float s3 = 1.0f / (1.0f + __expf(-t[3]));   // x0=1, x1=1
        s_c[o][q] = make_float4(s0, s1 - s0, s2 - s0, s3 - s1 - s2 + s0);
    }
    __syncthreads();

    const ull NEG1 = pack2(-1.0f, -1.0f);
    const int b0 = BPT * tid;   // this thread's first batch within the tile

    float res[OT][BPT];

#pragma unroll
    for (int o = 0; o < OT; o++) {
        // Gather: per dim, two 16B loads give 4 ready-packed f32x2 pairs.
        ull xv[4][NIN];
#pragma unroll
        for (int i = 0; i < NIN; i++) {
            const float* p = g_xT + s_off[o][i] + b0;
            ulonglong2 u = *(const ulonglong2*)p;        // batches b0..b0+3
            ulonglong2 v = *(const ulonglong2*)(p + 4);  // batches b0+4..b0+7
            xv[0][i] = u.x; xv[1][i] = u.y;
            xv[2][i] = v.x; xv[3][i] = v.y;
        }
        ull t01[4];
#pragma unroll
        for (int p = 0; p < 4; p++) t01[p] = mul2(xv[p][0], xv[p][1]);

        // Depth-first: 16 bilinear quads -> lerp tree levels 2..5, 4-wide.
        ull s2[4], s3[4], s4[4], rr[4];
#pragma unroll
        for (int g = 0; g < 8; g++) {
            ull u[4], v[4], e[4];
            {
                float4 c = s_c[o][2 * g];
                ull A   = pack2(c.x, c.x), D0  = pack2(c.y, c.y);
                ull D1  = pack2(c.z, c.z), D01 = pack2(c.w, c.w);
#pragma unroll
                for (int p = 0; p < 4; p++)
                    u[p] = fma2(t01[p], D01,
                           fma2(xv[p][1], D1, fma2(xv[p][0], D0, A)));
            }
            {
                float4 c = s_c[o][2 * g + 1];
                ull A   = pack2(c.x, c.x), D0  = pack2(c.y, c.y);
                ull D1  = pack2(c.z, c.z), D01 = pack2(c.w, c.w);
#pragma unroll
                for (int p = 0; p < 4; p++)
                    v[p] = fma2(t01[p], D01,
                           fma2(xv[p][1], D1, fma2(xv[p][0], D0, A)));
            }
#pragma unroll
            for (int p = 0; p < 4; p++) {
                ull d = fma2(u[p], NEG1, v[p]);
                e[p] = fma2(xv[p][2], d, u[p]);
            }
            if ((g & 1) == 0) {
#pragma unroll
                for (int p = 0; p < 4; p++) s2[p] = e[p];
            } else {
                ull f[4];
#pragma unroll
                for (int p = 0; p < 4; p++) {
                    ull d = fma2(s2[p], NEG1, e[p]);
                    f[p] = fma2(xv[p][3], d, s2[p]);
                }
                if ((g & 2) == 0) {
#pragma unroll
                    for (int p = 0; p < 4; p++) s3[p] = f[p];
                } else {
                    ull h[4];
#pragma unroll
                    for (int p = 0; p < 4; p++) {
                        ull d = fma2(s3[p], NEG1, f[p]);
                        h[p] = fma2(xv[p][4], d, s3[p]);
                    }
                    if ((g & 4) == 0) {
#pragma unroll
                        for (int p = 0; p < 4; p++) s4[p] = h[p];
                    } else {
#pragma unroll
                        for (int p = 0; p < 4; p++) {
                            ull d = fma2(s4[p], NEG1, h[p]);
                            rr[p] = fma2(xv[p][5], d, s4[p]);
                        }
                    }
                }
            }
        }
#pragma unroll
        for (int p = 0; p < 4; p++) {
            float2 f = unpack2(rr[p]);
            res[o][2 * p]     = f.x;
            res[o][2 * p + 1] = f.y;
        }
    }

    // Stores: per batch row, one float2 covering this thread's 2 outputs.
#pragma unroll
    for (int j = 0; j < BPT; j++)
        *(float2*)(out + (size_t)(bbase + b0 + j) * OSIZE + obase) =
            make_float2(res[0][j], res[1][j]);
}

// ---------------------------------------------------------------------------
extern "C" void kernel_launch(void* const* d_in, const int* in_sizes, int n_in,
                              void* d_out, int out_size) {
    const float* x     = (const float*)d_in[0];
    const float* table = (const float*)d_in[1];
    const void*  mraw  = d_in[2];
    float*       out   = (float*)d_out;

    (void)in_sizes; (void)n_in; (void)out_size;

    transpose_kernel<<<dim3(ISIZE / 32, BATCH / 32), dim3(32, 8)>>>(x);
    lut_kernel<<<dim3(OSIZE / OT, BATCH / BT), THREADS>>>(table, mraw, out);
}

// round 10
// speedup vs baseline: 1.4054x; 1.4054x over previous
#include <cuda_runtime.h>

#define BATCH 2048
#define ISIZE 2048
#define OSIZE 2048
#define NIN   6
#define KTAB  64

typedef unsigned long long ull;

// Static scratch: transposed x, xT[m][b]  (16 MB)
__device__ float g_xT[(size_t)ISIZE * BATCH];

__device__ __forceinline__ ull pack2(float lo, float hi) {
    ull r;
    asm("mov.b64 %0, {%1, %2};" : "=l"(r) : "f"(lo), "f"(hi));
    return r;
}
__device__ __forceinline__ ull dup2(float f) { return pack2(f, f); }
__device__ __forceinline__ ull fma2(ull a, ull b, ull c) {
    ull r;
    asm("fma.rn.f32x2 %0, %1, %2, %3;" : "=l"(r) : "l"(a), "l"(b), "l"(c));
    return r;
}
__device__ __forceinline__ float2 unpack2(ull v) {
    float2 f;
    asm("mov.b64 {%0, %1}, %2;" : "=f"(f.x), "=f"(f.y) : "l"(v));
    return f;
}

// ---------------------------------------------------------------------------
// Kernel 1: transpose x [BATCH][ISIZE] -> g_xT [ISIZE][BATCH]
// ---------------------------------------------------------------------------
__global__ void transpose_kernel(const float* __restrict__ x) {
    __shared__ float tile[32][33];
    int bx = blockIdx.x * 32;
    int by = blockIdx.y * 32;
    int tx = threadIdx.x, ty = threadIdx.y;
#pragma unroll
    for (int j = 0; j < 32; j += 8)
        tile[ty + j][tx] = x[(size_t)(by + ty + j) * ISIZE + bx + tx];
    __syncthreads();
#pragma unroll
    for (int j = 0; j < 32; j += 8)
        g_xT[(size_t)(bx + ty + j) * BATCH + by + tx] = tile[tx][ty + j];
}

// ---------------------------------------------------------------------------
// Kernel 2: LUT evaluation via Mobius-Horner.
//   Setup: sigmoid(table) -> in-place Mobius (finite-difference) transform
//   over the 6-bit lattice in shared. Then
//     out = sum_S m_S * prod_{i in S} x_i
//   evaluated as a binary Horner tree: every merge is ONE fma
//   (y = even + x*odd), 63 FFMA2 per (o, batch-pair) vs 79 for the lerp tree.
//   Thread tile: 4 outputs x 4 contiguous batches (2 f32x2 pairs).
//   Gathers: one 16B load per (o,dim) yields both pre-packed pairs.
//   Grid 512 x 4 = 2048 CTAs; 7 CTAs/SM pinned via launch bounds.
// ---------------------------------------------------------------------------
#define OT      4
#define THREADS 128
#define BPT     4
#define BT      (THREADS * BPT)   // 512
#define NQ      (KTAB / 4)        // 16

__global__ __launch_bounds__(THREADS, 7)
void lut_kernel(const float* __restrict__ table,
                const void* __restrict__ mraw,
                float* __restrict__ out) {
    __shared__ __align__(16) float s_m[OT][KTAB];   // Mobius coeffs
    __shared__ int s_off[OT][NIN];
    __shared__ int s_is64;

    const int tid   = threadIdx.x;
    const int obase = blockIdx.x * OT;
    const int bbase = blockIdx.y * BT;

    // Detect mapping dtype: int64 values < 2048 => odd 32-bit words are 0.
    const int* w32 = (const int*)mraw;
    if (tid == 0) {
        int z = 1;
#pragma unroll
        for (int i = 1; i < 16; i += 2) z &= (w32[i] == 0);
        s_is64 = z;
    }
    __syncthreads();
    const int is64 = s_is64;

    if (tid < OT * NIN) {
        int idx = (obase + tid / NIN) * NIN + (tid % NIN);
        int m = is64 ? (int)((const long long*)mraw)[idx] : w32[idx];
        s_off[tid / NIN][tid % NIN] = m * BATCH + bbase;
    }

    // Sigmoid of the table tile (OT*KTAB = 256 entries, 2 per thread).
    float* mf = &s_m[0][0];
#pragma unroll
    for (int i = tid; i < OT * KTAB; i += THREADS) {
        float t = table[(size_t)(obase + (i >> 6)) * KTAB + (i & 63)];
        mf[i] = 1.0f / (1.0f + __expf(-t));
    }
    // In-place Mobius transform over the 6 index bits (per output row).
#pragma unroll
    for (int bit = 0; bit < NIN; bit++) {
        __syncthreads();
        int msk = 1 << bit;
#pragma unroll
        for (int i = tid; i < OT * KTAB; i += THREADS) {
            if (i & msk) mf[i] -= mf[i ^ msk];
        }
    }
    __syncthreads();

    const int b0 = BPT * tid;   // 4 contiguous batches

    float res[OT][BPT];

#pragma unroll
    for (int o = 0; o < OT; o++) {
        // Gather: one 16B load per dim => two pre-packed f32x2 pairs.
        ull xv[2][NIN];
#pragma unroll
        for (int i = 0; i < NIN; i++) {
            ulonglong2 u = *(const ulonglong2*)(g_xT + s_off[o][i] + b0);
            xv[0][i] = u.x;
            xv[1][i] = u.y;
        }

        const float4* c4 = (const float4*)&s_m[o][0];

        // Depth-first Horner tree: quads (bits 0-1) then merges (bits 2-5),
        // each merge a single fma: y = even + x * odd.
        ull st2[2], st3[2], st4[2], rr[2];
#pragma unroll
        for (int t = 0; t < 8; t++) {
            ull w0[2], w1[2], y[2];
            {
                float4 c = c4[2 * t];
                ull C0 = dup2(c.x), C1 = dup2(c.y), C2 = dup2(c.z), C3 = dup2(c.w);
#pragma unroll
                for (int p = 0; p < 2; p++) {
                    ull u = fma2(xv[p][0], C1, C0);
                    ull v = fma2(xv[p][0], C3, C2);
                    w0[p] = fma2(xv[p][1], v, u);
                }
            }
            {
                float4 c = c4[2 * t + 1];
                ull C0 = dup2(c.x), C1 = dup2(c.y), C2 = dup2(c.z), C3 = dup2(c.w);
#pragma unroll
                for (int p = 0; p < 2; p++) {
                    ull u = fma2(xv[p][0], C1, C0);
                    ull v = fma2(xv[p][0], C3, C2);
                    w1[p] = fma2(xv[p][1], v, u);
                }
            }
#pragma unroll
            for (int p = 0; p < 2; p++) y[p] = fma2(xv[p][2], w1[p], w0[p]);
            if ((t & 1) == 0) {
                st2[0] = y[0]; st2[1] = y[1];
            } else {
#pragma unroll
                for (int p = 0; p < 2; p++) y[p] = fma2(xv[p][3], y[p], st2[p]);
                if ((t & 2) == 0) {
                    st3[0] = y[0]; st3[1] = y[1];
                } else {
#pragma unroll
                    for (int p = 0; p < 2; p++) y[p] = fma2(xv[p][4], y[p], st3[p]);
                    if ((t & 4) == 0) {
                        st4[0] = y[0]; st4[1] = y[1];
                    } else {
#pragma unroll
                        for (int p = 0; p < 2; p++)
                            rr[p] = fma2(xv[p][5], y[p], st4[p]);
                    }
                }
            }
        }

        float2 f0 = unpack2(rr[0]), f1 = unpack2(rr[1]);
        res[o][0] = f0.x; res[o][1] = f0.y;
        res[o][2] = f1.x; res[o][3] = f1.y;
    }

    // 16B contiguous per batch row (4 outputs), 4 rows per thread.
#pragma unroll
    for (int j = 0; j < BPT; j++)
        *(float4*)(out + (size_t)(bbase + b0 + j) * OSIZE + obase) =
            make_float4(res[0][j], res[1][j], res[2][j], res[3][j]);
}

// ---------------------------------------------------------------------------
extern "C" void kernel_launch(void* const* d_in, const int* in_sizes, int n_in,
                              void* d_out, int out_size) {
    const float* x     = (const float*)d_in[0];
    const float* table = (const float*)d_in[1];
    const void*  mraw  = d_in[2];
    float*       out   = (float*)d_out;

    (void)in_sizes; (void)n_in; (void)out_size;

    transpose_kernel<<<dim3(ISIZE / 32, BATCH / 32), dim3(32, 8)>>>(x);
    lut_kernel<<<dim3(OSIZE / OT, BATCH / BT), THREADS>>>(table, mraw, out);
}

// round 13
// speedup vs baseline: 1.4186x; 1.0094x over previous
#include <cuda_runtime.h>

#define BATCH 2048
#define ISIZE 2048
#define OSIZE 2048
#define NIN   6
#define KTAB  64

typedef unsigned long long ull;

// Static scratch: transposed x, xT[m][b]  (16 MB)
__device__ float g_xT[(size_t)ISIZE * BATCH];

__device__ __forceinline__ ull pack2(float lo, float hi) {
    ull r;
    asm("mov.b64 %0, {%1, %2};" : "=l"(r) : "f"(lo), "f"(hi));
    return r;
}
__device__ __forceinline__ ull dup2(float f) { return pack2(f, f); }
__device__ __forceinline__ ull fma2(ull a, ull b, ull c) {
    ull r;
    asm("fma.rn.f32x2 %0, %1, %2, %3;" : "=l"(r) : "l"(a), "l"(b), "l"(c));
    return r;
}
__device__ __forceinline__ float2 unpack2(ull v) {
    float2 f;
    asm("mov.b64 {%0, %1}, %2;" : "=f"(f.x), "=f"(f.y) : "l"(v));
    return f;
}

// ---------------------------------------------------------------------------
// Kernel 1: transpose x [BATCH][ISIZE] -> g_xT [ISIZE][BATCH]
// ---------------------------------------------------------------------------
__global__ void transpose_kernel(const float* __restrict__ x) {
    __shared__ float tile[32][33];
    int bx = blockIdx.x * 32;
    int by = blockIdx.y * 32;
    int tx = threadIdx.x, ty = threadIdx.y;
#pragma unroll
    for (int j = 0; j < 32; j += 8)
        tile[ty + j][tx] = x[(size_t)(by + ty + j) * ISIZE + bx + tx];
    __syncthreads();
#pragma unroll
    for (int j = 0; j < 32; j += 8)
        g_xT[(size_t)(bx + ty + j) * BATCH + by + tx] = tile[tx][ty + j];
}

// ---------------------------------------------------------------------------
// Kernel 2: LUT evaluation via Mobius-Horner, with gathers software-pipelined
// across the o loop:
//   - dims 0-2 of o+1 prefetched during o's tree (double-buffered, +12 regs)
//   - dims 3-5 of o loaded at tree start (first consumed ~25+ instrs later,
//     latency self-hiding)
//   Thread tile: 4 outputs x 4 contiguous batches (2 f32x2 pairs).
//   Grid 512 x 4 = 2048 CTAs; launch_bounds caps regs at 85 (6 CTAs/SM).
// ---------------------------------------------------------------------------
#define OT      4
#define THREADS 128
#define BPT     4
#define BT      (THREADS * BPT)   // 512

__global__ __launch_bounds__(THREADS, 6)
void lut_kernel(const float* __restrict__ table,
                const void* __restrict__ mraw,
                float* __restrict__ out) {
    __shared__ __align__(16) float s_m[OT][KTAB];   // Mobius coeffs
    __shared__ int s_off[OT][NIN];
    __shared__ int s_is64;

    const int tid   = threadIdx.x;
    const int obase = blockIdx.x * OT;
    const int bbase = blockIdx.y * BT;

    // Detect mapping dtype: int64 values < 2048 => odd 32-bit words are 0.
    const int* w32 = (const int*)mraw;
    if (tid == 0) {
        int z = 1;
#pragma unroll
        for (int i = 1; i < 16; i += 2) z &= (w32[i] == 0);
        s_is64 = z;
    }
    __syncthreads();
    const int is64 = s_is64;

    if (tid < OT * NIN) {
        int idx = (obase + tid / NIN) * NIN + (tid % NIN);
        int m = is64 ? (int)((const long long*)mraw)[idx] : w32[idx];
        s_off[tid / NIN][tid % NIN] = m * BATCH + bbase;
    }

    // Sigmoid of the table tile (OT*KTAB = 256 entries).
    float* mf = &s_m[0][0];
#pragma unroll
    for (int i = tid; i < OT * KTAB; i += THREADS) {
        float t = table[(size_t)(obase + (i >> 6)) * KTAB + (i & 63)];
        mf[i] = 1.0f / (1.0f + __expf(-t));
    }
    // In-place Mobius transform over the 6 index bits (per output row).
#pragma unroll
    for (int bit = 0; bit < NIN; bit++) {
        __syncthreads();
        int msk = 1 << bit;
#pragma unroll
        for (int i = tid; i < OT * KTAB; i += THREADS) {
            if (i & msk) mf[i] -= mf[i ^ msk];
        }
    }
    __syncthreads();

    const int b0 = BPT * tid;   // 4 contiguous batches

    float res[OT][BPT];

    // Prologue: prefetch dims 0-2 for o = 0.
    ull P[2][3];
#pragma unroll
    for (int i = 0; i < 3; i++) {
        ulonglong2 u = *(const ulonglong2*)(g_xT + s_off[0][i] + b0);
        P[0][i] = u.x; P[1][i] = u.y;
    }

#pragma unroll
    for (int o = 0; o < OT; o++) {
        // Late dims for this o (consumed deep in the tree).
        ull X3[2], X4[2], X5[2];
        {
            ulonglong2 u3 = *(const ulonglong2*)(g_xT + s_off[o][3] + b0);
            ulonglong2 u4 = *(const ulonglong2*)(g_xT + s_off[o][4] + b0);
            ulonglong2 u5 = *(const ulonglong2*)(g_xT + s_off[o][5] + b0);
            X3[0] = u3.x; X3[1] = u3.y;
            X4[0] = u4.x; X4[1] = u4.y;
            X5[0] = u5.x; X5[1] = u5.y;
        }
        // Prefetch dims 0-2 for o+1 (hidden under this o's tree).
        ull PN[2][3];
        if (o + 1 < OT) {
#pragma unroll
            for (int i = 0; i < 3; i++) {
                ulonglong2 u = *(const ulonglong2*)(g_xT + s_off[o + 1][i] + b0);
                PN[0][i] = u.x; PN[1][i] = u.y;
            }
        }

        const float4* c4 = (const float4*)&s_m[o][0];

        // Depth-first Horner tree: quads (bits 0-1) then merges (bits 2-5),
        // each merge a single fma: y = even + x * odd.
        ull st2[2], st3[2], st4[2], rr[2];
#pragma unroll
        for (int t = 0; t < 8; t++) {
            ull w0[2], w1[2], y[2];
            {
                float4 c = c4[2 * t];
                ull C0 = dup2(c.x), C1 = dup2(c.y), C2 = dup2(c.z), C3 = dup2(c.w);
#pragma unroll
                for (int p = 0; p < 2; p++) {
                    ull u = fma2(P[p][0], C1, C0);
                    ull v = fma2(P[p][0], C3, C2);
                    w0[p] = fma2(P[p][1], v, u);
                }
            }
            {
                float4 c = c4[2 * t + 1];
                ull C0 = dup2(c.x), C1 = dup2(c.y), C2 = dup2(c.z), C3 = dup2(c.w);
#pragma unroll
                for (int p = 0; p < 2; p++) {
                    ull u = fma2(P[p][0], C1, C0);
                    ull v = fma2(P[p][0], C3, C2);
                    w1[p] = fma2(P[p][1], v, u);
                }
            }
#pragma unroll
            for (int p = 0; p < 2; p++) y[p] = fma2(P[p][2], w1[p], w0[p]);
            if ((t & 1) == 0) {
                st2[0] = y[0]; st2[1] = y[1];
            } else {
#pragma unroll
                for (int p = 0; p < 2; p++) y[p] = fma2(X3[p], y[p], st2[p]);
                if ((t & 2) == 0) {
                    st3[0] = y[0]; st3[1] = y[1];
                } else {
#pragma unroll
                    for (int p = 0; p < 2; p++) y[p] = fma2(X4[p], y[p], st3[p]);
                    if ((t & 4) == 0) {
                        st4[0] = y[0]; st4[1] = y[1];
                    } else {
#pragma unroll
                        for (int p = 0; p < 2; p++)
                            rr[p] = fma2(X5[p], y[p], st4[p]);
                    }
                }
            }
        }

        float2 f0 = unpack2(rr[0]), f1 = unpack2(rr[1]);
        res[o][0] = f0.x; res[o][1] = f0.y;
        res[o][2] = f1.x; res[o][3] = f1.y;

        // Rotate prefetch buffer.
        if (o + 1 < OT) {
#pragma unroll
            for (int i = 0; i < 3; i++) {
                P[0][i] = PN[0][i];
                P[1][i] = PN[1][i];
            }
        }
    }

    // 16B contiguous per batch row (4 outputs), 4 rows per thread.
#pragma unroll
    for (int j = 0; j < BPT; j++)
        *(float4*)(out + (size_t)(bbase + b0 + j) * OSIZE + obase) =
            make_float4(res[0][j], res[1][j], res[2][j], res[3][j]);
}

// ---------------------------------------------------------------------------
extern "C" void kernel_launch(void* const* d_in, const int* in_sizes, int n_in,
                              void* d_out, int out_size) {
    const float* x     = (const float*)d_in[0];
    const float* table = (const float*)d_in[1];
    const void*  mraw  = d_in[2];
    float*       out   = (float*)d_out;

    (void)in_sizes; (void)n_in; (void)out_size;

    transpose_kernel<<<dim3(ISIZE / 32, BATCH / 32), dim3(32, 8)>>>(x);
    lut_kernel<<<dim3(OSIZE / OT, BATCH / BT), THREADS>>>(table, mraw, out);
}